// round 11
// baseline (speedup 1.0000x reference)
#include <cuda_runtime.h>
#include <cuda_fp16.h>
#include <cstdint>

// Problem constants
#define BB 8
#define NN 2048
#define FF 256
#define CHUNKS (NN / 64)

// Scratch (allocation-free rule: __device__ globals)
__device__ __half g_xh[BB * NN * FF];    // x in f16              8.4 MB
__device__ __half g_Wh[FF * FF];         // W in f16
__device__ __half g_hTh[BB * FF * NN];   // h f16, [b][f][n]      8.4 MB
__device__ float g_wsrc[FF];             // W^T a_src
__device__ float g_wdst[FF];             // W^T a_dst
__device__ float g_es1[BB * NN];         // exp(s_src)
__device__ float g_es2[BB * NN];         // exp(0.2*s_src)
__device__ float g_ed1[BB * NN];         // exp(s_dst)
__device__ float g_ed2[BB * NN];         // exp(0.2*s_dst)

// ---------------------------------------------------------------------------
// helpers
// ---------------------------------------------------------------------------
__device__ __forceinline__ uint32_t smem_u32(const void* p) {
    uint32_t a;
    asm("{ .reg .u64 t; cvta.to.shared.u64 t, %1; cvt.u32.u64 %0, t; }"
        : "=r"(a) : "l"(p));
    return a;
}

__device__ __forceinline__ void cp16(uint32_t dst, const void* src) {
    asm volatile(
        "{ .reg .u64 g; cvta.to.global.u64 g, %1;"
        "  cp.async.cg.shared.global [%0], [g], 16; }"
        ::"r"(dst), "l"(src) : "memory");
}
#define CP_COMMIT() asm volatile("cp.async.commit_group;" ::: "memory")
#define CP_WAIT1() asm volatile("cp.async.wait_group 1;" ::: "memory")
#define CP_WAIT0() asm volatile("cp.async.wait_group 0;" ::: "memory")

__device__ __forceinline__ void ldsm4(uint32_t* r, uint32_t a) {
    asm volatile("ldmatrix.sync.aligned.m8n8.x4.shared.b16 {%0,%1,%2,%3}, [%4];"
                 : "=r"(r[0]), "=r"(r[1]), "=r"(r[2]), "=r"(r[3]) : "r"(a));
}

__device__ __forceinline__ void mma_f16(float* d, const uint32_t* a, uint32_t b0,
                                        uint32_t b1) {
    asm volatile(
        "mma.sync.aligned.m16n8k16.row.col.f32.f16.f16.f32 "
        "{%0,%1,%2,%3}, {%4,%5,%6,%7}, {%8,%9}, {%0,%1,%2,%3};"
        : "+f"(d[0]), "+f"(d[1]), "+f"(d[2]), "+f"(d[3])
        : "r"(a[0]), "r"(a[1]), "r"(a[2]), "r"(a[3]), "r"(b0), "r"(b1));
}

// tile row stride: 64 f16 + 8 pad = 144 bytes (9 x 16B -> conflict-free LDSM)
#define TSTRIDE 144

// ---------------------------------------------------------------------------
// wvec + cvt_w: w_src[k] = sum_o a_src[o]*W[o][k] (warp per k, 256 warps),
// plus f32->f16 conversion of W in the same kernel.
// ---------------------------------------------------------------------------
__global__ __launch_bounds__(256) void wvec_cvtw_kernel(const float* __restrict__ W,
                                                        const float* __restrict__ a_src,
                                                        const float* __restrict__ a_dst) {
    int t = threadIdx.x, lane = t & 31, warp = t >> 5;
    int k = blockIdx.x * 8 + warp;     // 0..255
    float s1 = 0.f, s2 = 0.f;
    #pragma unroll
    for (int q = 0; q < 8; q++) {
        int o = lane + 32 * q;
        float w = W[(size_t)o * FF + k];
        s1 += a_src[o] * w;
        s2 += a_dst[o] * w;
    }
    #pragma unroll
    for (int o = 16; o; o >>= 1) {
        s1 += __shfl_xor_sync(0xFFFFFFFFu, s1, o);
        s2 += __shfl_xor_sync(0xFFFFFFFFu, s2, o);
    }
    if (lane == 0) {
        g_wsrc[k] = s1;
        g_wdst[k] = s2;
    }
    const float4* src = reinterpret_cast<const float4*>(W);
    __half2* dst = reinterpret_cast<__half2*>(g_Wh);
    int gt = blockIdx.x * 256 + t;
    #pragma unroll
    for (int q = 0; q < 2; q++) {
        int i = gt + 8192 * q;
        float4 v = src[i];
        dst[i * 2] = __floats2half2_rn(v.x, v.y);
        dst[i * 2 + 1] = __floats2half2_rn(v.z, v.w);
    }
}

// ---------------------------------------------------------------------------
// score + cvt_x: s_src = x.w_src, s_dst = x.w_dst (warp per row), and emit
// the f16 copy of x while the row is in registers.
// ---------------------------------------------------------------------------
__global__ __launch_bounds__(256) void score_kernel(const float* __restrict__ x) {
    __shared__ float ws[FF], wd[FF];
    int t = threadIdx.x;
    ws[t] = g_wsrc[t];
    wd[t] = g_wdst[t];
    __syncthreads();
    int warp = t >> 5, lane = t & 31;
    int g = blockIdx.x * 8 + warp;
    const float4* xr = reinterpret_cast<const float4*>(x + (size_t)g * FF);
    __half2* xo = reinterpret_cast<__half2*>(g_xh + (size_t)g * FF);
    float s1 = 0.f, s2 = 0.f;
    #pragma unroll
    for (int q = 0; q < 2; q++) {
        int idx = lane + 32 * q;
        float4 v = xr[idx];
        xo[idx * 2] = __floats2half2_rn(v.x, v.y);
        xo[idx * 2 + 1] = __floats2half2_rn(v.z, v.w);
        float4 w1 = *reinterpret_cast<const float4*>(&ws[idx * 4]);
        float4 w2 = *reinterpret_cast<const float4*>(&wd[idx * 4]);
        s1 += v.x * w1.x + v.y * w1.y + v.z * w1.z + v.w * w1.w;
        s2 += v.x * w2.x + v.y * w2.y + v.z * w2.z + v.w * w2.w;
    }
    #pragma unroll
    for (int o = 16; o; o >>= 1) {
        s1 += __shfl_xor_sync(0xFFFFFFFFu, s1, o);
        s2 += __shfl_xor_sync(0xFFFFFFFFu, s2, o);
    }
    if (lane == 0) {
        g_es1[g] = __expf(s1);
        g_es2[g] = __expf(0.2f * s1);
        g_ed1[g] = __expf(s2);
        g_ed2[g] = __expf(0.2f * s2);
    }
}

// ---------------------------------------------------------------------------
// gemm_h: h_T[b][f][n] = sum_k W[f][k] * x[b][n][k]   (f16 mma, f32 accum)
// ---------------------------------------------------------------------------
#define GH_SMEM (4 * 128 * TSTRIDE)   // A0,A1,B0,B1 each 128*144
__global__ __launch_bounds__(256, 2) void gemm_h_kernel() {
    extern __shared__ char smraw[];
    uint32_t su = smem_u32(smraw);
    const uint32_t AB[2] = {su, su + 128 * TSTRIDE};
    const uint32_t XB[2] = {su + 2 * 128 * TSTRIDE, su + 3 * 128 * TSTRIDE};

    int t = threadIdx.x, l = t & 31, w = t >> 5;
    int b = blockIdx.z, n0 = blockIdx.x * 128, m0 = blockIdx.y * 128;
    int mbase = (w & 1) * 64, nbase = (w >> 1) * 32;
    int a_row = (l & 7) + ((l & 8) ? 8 : 0);
    int a_k = (l & 16) ? 16 : 0;
    int b_row = (l & 7) + ((l & 16) ? 8 : 0);
    int b_k = (l & 8) ? 16 : 0;

    const __half* Wsrc = g_Wh + (size_t)m0 * FF;
    const __half* Xsrc = g_xh + ((size_t)b * NN + n0) * FF;
    int fr = t >> 1, fs = (t & 1) * 4;  // 2 threads/row, 4 segs each

    float acc[4][4][4] = {};

    #define GH_FILL(kc, s)                                                   \
        do {                                                                 \
            _Pragma("unroll")                                                \
            for (int q = 0; q < 4; q++) {                                    \
                cp16(AB[s] + fr * TSTRIDE + (fs + q) * 16,                   \
                     Wsrc + (size_t)fr * FF + (kc) + (fs + q) * 8);          \
                cp16(XB[s] + fr * TSTRIDE + (fs + q) * 16,                   \
                     Xsrc + (size_t)fr * FF + (kc) + (fs + q) * 8);          \
            }                                                                \
            CP_COMMIT();                                                     \
        } while (0)

    GH_FILL(0, 0);
    for (int c = 0; c < 4; c++) {
        int s = c & 1;
        if (c < 3) GH_FILL((c + 1) * 64, s ^ 1);
        if (c < 3) CP_WAIT1(); else CP_WAIT0();
        __syncthreads();
        #pragma unroll
        for (int kk = 0; kk < 4; kk++) {
            uint32_t bf[2][4];
            #pragma unroll
            for (int g = 0; g < 2; g++)
                ldsm4(bf[g], XB[s] + (nbase + g * 16 + b_row) * TSTRIDE +
                                 kk * 32 + b_k);
            #pragma unroll
            for (int mt = 0; mt < 4; mt++) {
                uint32_t a[4];
                ldsm4(a, AB[s] + (mbase + mt * 16 + a_row) * TSTRIDE +
                             kk * 32 + a_k);
                #pragma unroll
                for (int g = 0; g < 2; g++) {
                    mma_f16(acc[mt][2 * g], a, bf[g][0], bf[g][1]);
                    mma_f16(acc[mt][2 * g + 1], a, bf[g][2], bf[g][3]);
                }
            }
        }
        __syncthreads();
    }

    #pragma unroll
    for (int mt = 0; mt < 4; mt++) {
        int f = m0 + mbase + mt * 16 + (l >> 2);
        #pragma unroll
        for (int nt = 0; nt < 4; nt++) {
            int n = n0 + nbase + nt * 8 + 2 * (l & 3);
            *reinterpret_cast<__half2*>(&g_hTh[((size_t)b * FF + f) * NN + n]) =
                __floats2half2_rn(acc[mt][nt][0], acc[mt][nt][1]);
            *reinterpret_cast<__half2*>(&g_hTh[((size_t)b * FF + f + 8) * NN + n]) =
                __floats2half2_rn(acc[mt][nt][2], acc[mt][nt][3]);
        }
    }
}

// ---------------------------------------------------------------------------
// attn: fused masked softmax + alpha @ h, f16 mma.
// ITILE=64, 256 threads = 8 warps (2i x 4n), warp tile m32 x n64 (fatter tile
// -> 25% less LDSM traffic: A re-read 4x, B 2x). 2 CTAs/SM, 16 warps/SM.
// Two-sync pipeline (proven): p(c) -> adj prefetch -> HFILL(c+1) -> WAIT1 ->
// sync -> mma(c) -> sync.
// p = adj * max(e^s_src * e^s_dst, e^{.2 s_src} * e^{.2 s_dst})  (exact lrelu)
// ---------------------------------------------------------------------------
#define ITILE 64
#define OFF_P0 0
#define OFF_P1 (64 * TSTRIDE)                       // 9216
#define OFF_H0 (2 * 64 * TSTRIDE)                   // 18432
#define OFF_H1 (OFF_H0 + 256 * TSTRIDE)             // 55296
#define OFF_SE (OFF_H1 + 256 * TSTRIDE)             // 92160
#define OFF_SG (OFF_SE + NN * 4)                    // 100352
#define OFF_ES1 (OFF_SG + NN * 4)                   // 108544
#define OFF_ES2 (OFF_ES1 + 256)
#define OFF_INVD (OFF_ES2 + 256)
#define AT_SMEM (OFF_INVD + 256)                    // 109312

__global__ __launch_bounds__(256, 2) void attn_kernel(const int* __restrict__ adj,
                                                      float* __restrict__ out) {
    extern __shared__ char smraw[];
    uint32_t su = smem_u32(smraw);
    float* sE = reinterpret_cast<float*>(smraw + OFF_SE);
    float* sG = reinterpret_cast<float*>(smraw + OFF_SG);
    float* eS1 = reinterpret_cast<float*>(smraw + OFF_ES1);
    float* eS2 = reinterpret_cast<float*>(smraw + OFF_ES2);
    float* invd = reinterpret_cast<float*>(smraw + OFF_INVD);

    int t = threadIdx.x, l = t & 31, w = t >> 5;
    int b = blockIdx.y;
    int i0 = blockIdx.x * ITILE;

    for (int c = t; c < NN; c += 256) {
        sE[c] = g_ed1[b * NN + c];
        sG[c] = g_ed2[b * NN + c];
    }
    if (t < ITILE) {
        eS1[t] = g_es1[b * NN + i0 + t];
        eS2[t] = g_es2[b * NN + i0 + t];
    }
    __syncthreads();

    // p mapping: 4 threads/row, 16 j each (4 int4 quads)
    int pi = t >> 2, jq = t & 3;
    float E1 = eS1[pi], E2 = eS2[pi];
    const int4* adj_row = reinterpret_cast<const int4*>(
                              adj + ((size_t)b * NN + i0 + pi) * NN) + jq * 4;
    const float4* sE4 = reinterpret_cast<const float4*>(sE);
    const float4* sG4 = reinterpret_cast<const float4*>(sG);
    float dreg = 0.f;

    // mma mapping: 2i x 4n warp grid, warp m32 x n64
    int mbase = (w & 1) * 32, nbase = (w >> 1) * 64;
    int a_row = (l & 7) + ((l & 8) ? 8 : 0);
    int a_k = (l & 16) ? 16 : 0;
    int b_row = (l & 7) + ((l & 16) ? 8 : 0);
    int b_k = (l & 8) ? 16 : 0;

    const __half* hsrc = g_hTh + (size_t)b * FF * NN;

    const uint32_t PB[2] = {su + OFF_P0, su + OFF_P1};
    const uint32_t HB[2] = {su + OFF_H0, su + OFF_H1};

    #define AT_HFILL(jc, s)                                                  \
        do {                                                                 \
            _Pragma("unroll")                                                \
            for (int l2 = 0; l2 < 8; l2++) {                                 \
                int e = t + 256 * l2;                                        \
                int fr = e >> 3, sg = e & 7;                                 \
                cp16(HB[s] + fr * TSTRIDE + sg * 16,                         \
                     hsrc + (size_t)fr * NN + (jc) + sg * 8);                \
            }                                                                \
            CP_COMMIT();                                                     \
        } while (0)

    int4 aR[4];
    #pragma unroll
    for (int q = 0; q < 4; q++) aR[q] = adj_row[q];
    AT_HFILL(0, 0);

    float acc[2][8][4] = {};

    for (int c = 0; c < CHUNKS; c++) {
        int s = c & 1;
        int jc = c * 64;

        // ---- p(c) from prefetched adj regs ----
        {
            uint32_t pk[8];
            int jb = (jc >> 2) + jq * 4;
            #pragma unroll
            for (int q = 0; q < 4; q++) {
                int4 av = aR[q];
                float4 de = sE4[jb + q];
                float4 dg = sG4[jb + q];
                float p0 = fmaxf(E1 * de.x, E2 * dg.x);
                float p1 = fmaxf(E1 * de.y, E2 * dg.y);
                float p2 = fmaxf(E1 * de.z, E2 * dg.z);
                float p3 = fmaxf(E1 * de.w, E2 * dg.w);
                p0 = av.x ? p0 : 0.f;
                p1 = av.y ? p1 : 0.f;
                p2 = av.z ? p2 : 0.f;
                p3 = av.w ? p3 : 0.f;
                __half2 h0 = __floats2half2_rn(p0, p1);
                __half2 h1 = __floats2half2_rn(p2, p3);
                float2 f0 = __half22float2(h0);
                float2 f1 = __half22float2(h1);
                dreg += (f0.x + f0.y) + (f1.x + f1.y);
                pk[q * 2] = *reinterpret_cast<uint32_t*>(&h0);
                pk[q * 2 + 1] = *reinterpret_cast<uint32_t*>(&h1);
            }
            uint32_t pa = PB[s] + pi * TSTRIDE + jq * 32;
            asm volatile("st.shared.v4.b32 [%0], {%1,%2,%3,%4};" ::"r"(pa),
                         "r"(pk[0]), "r"(pk[1]), "r"(pk[2]), "r"(pk[3]) : "memory");
            asm volatile("st.shared.v4.b32 [%0], {%1,%2,%3,%4};" ::"r"(pa + 16),
                         "r"(pk[4]), "r"(pk[5]), "r"(pk[6]), "r"(pk[7]) : "memory");
        }
        // ---- prefetch adj(c+1), issue h(c+1) cp.async ----
        if (c + 1 < CHUNKS) {
            #pragma unroll
            for (int q = 0; q < 4; q++) aR[q] = adj_row[(c + 1) * 16 + q];
            AT_HFILL(jc + 64, s ^ 1);
            CP_WAIT1();
        } else {
            CP_WAIT0();
        }
        __syncthreads();

        // ---- f16 tensor-core GEMM on buffers s (m32 x n64 per warp) ----
        #pragma unroll
        for (int kk = 0; kk < 4; kk++) {
            uint32_t bf[4][4];
            #pragma unroll
            for (int g = 0; g < 4; g++)
                ldsm4(bf[g], HB[s] + (nbase + g * 16 + b_row) * TSTRIDE +
                                 kk * 32 + b_k);
            #pragma unroll
            for (int mt = 0; mt < 2; mt++) {
                uint32_t a[4];
                ldsm4(a, PB[s] + (mbase + mt * 16 + a_row) * TSTRIDE +
                             kk * 32 + a_k);
                #pragma unroll
                for (int g = 0; g < 4; g++) {
                    mma_f16(acc[mt][2 * g], a, bf[g][0], bf[g][1]);
                    mma_f16(acc[mt][2 * g + 1], a, bf[g][2], bf[g][3]);
                }
            }
        }
        __syncthreads();
    }

    // ---- denominators (4 threads per row -> shfl over 2 levels) ----
    dreg += __shfl_xor_sync(0xFFFFFFFFu, dreg, 1);
    dreg += __shfl_xor_sync(0xFFFFFFFFu, dreg, 2);
    if ((t & 3) == 0) invd[pi] = (dreg > 0.f) ? (1.f / dreg) : 0.f;
    __syncthreads();

    // ---- epilogue ----
    #pragma unroll
    for (int mt = 0; mt < 2; mt++) {
        int lr = mbase + mt * 16 + (l >> 2);
        float s0 = invd[lr], s1v = invd[lr + 8];
        float* o0 = out + ((size_t)b * NN + i0 + lr) * FF + nbase;
        float* o1 = o0 + (size_t)8 * FF;
        #pragma unroll
        for (int nt = 0; nt < 8; nt++) {
            int cofs = nt * 8 + 2 * (l & 3);
            *reinterpret_cast<float2*>(o0 + cofs) =
                make_float2(acc[mt][nt][0] * s0, acc[mt][nt][1] * s0);
            *reinterpret_cast<float2*>(o1 + cofs) =
                make_float2(acc[mt][nt][2] * s1v, acc[mt][nt][3] * s1v);
        }
    }
}

// ---------------------------------------------------------------------------
extern "C" void kernel_launch(void* const* d_in, const int* in_sizes, int n_in,
                              void* d_out, int out_size) {
    const float* x     = (const float*)d_in[0];  // (B,N,F_in)
    const int*   adj   = (const int*)d_in[1];    // (B,N,N)
    const float* W     = (const float*)d_in[2];  // (F_out,F_in)
    const float* a_src = (const float*)d_in[3];  // (F_out)
    const float* a_dst = (const float*)d_in[4];  // (F_out)
    float* out = (float*)d_out;                  // (B,N,F_out)

    (void)in_sizes; (void)n_in; (void)out_size;

    // w = W^T a (warp-per-k) + W f16 conversion, one kernel
    wvec_cvtw_kernel<<<32, 256>>>(W, a_src, a_dst);
    // scores + x f16 conversion, one kernel
    score_kernel<<<(BB * NN) / 8, 256>>>(x);
    // h_T = W @ x^T (f16 tensor cores)
    cudaFuncSetAttribute(gemm_h_kernel, cudaFuncAttributeMaxDynamicSharedMemorySize,
                         GH_SMEM);
    gemm_h_kernel<<<dim3(NN / 128, FF / 128, BB), 256, GH_SMEM>>>();
    // fused masked softmax + alpha @ h (two-sync, 8 warps m32xn64, 2 CTAs/SM)
    cudaFuncSetAttribute(attn_kernel, cudaFuncAttributeMaxDynamicSharedMemorySize,
                         AT_SMEM);
    attn_kernel<<<dim3(NN / ITILE, BB), 256, AT_SMEM>>>(adj, out);
}

// round 12
// speedup vs baseline: 1.1133x; 1.1133x over previous
#include <cuda_runtime.h>
#include <cuda_fp16.h>
#include <cstdint>

// Problem constants
#define BB 8
#define NN 2048
#define FF 256
#define CHUNKS (NN / 64)

// Scratch (allocation-free rule: __device__ globals)
__device__ __half g_xh[BB * NN * FF];    // x in f16              8.4 MB
__device__ __half g_Wh[FF * FF];         // W in f16
__device__ __half g_hTh[BB * FF * NN];   // h f16, [b][f][n]      8.4 MB
__device__ float g_wsrc[FF];             // W^T a_src
__device__ float g_wdst[FF];             // W^T a_dst
__device__ float g_es1[BB * NN];         // exp(s_src)
__device__ float g_es2[BB * NN];         // exp(0.2*s_src)
__device__ float g_ed1[BB * NN];         // exp(s_dst)
__device__ float g_ed2[BB * NN];         // exp(0.2*s_dst)

// ---------------------------------------------------------------------------
// helpers
// ---------------------------------------------------------------------------
__device__ __forceinline__ uint32_t smem_u32(const void* p) {
    uint32_t a;
    asm("{ .reg .u64 t; cvta.to.shared.u64 t, %1; cvt.u32.u64 %0, t; }"
        : "=r"(a) : "l"(p));
    return a;
}

__device__ __forceinline__ void cp16(uint32_t dst, const void* src) {
    asm volatile(
        "{ .reg .u64 g; cvta.to.global.u64 g, %1;"
        "  cp.async.cg.shared.global [%0], [g], 16; }"
        ::"r"(dst), "l"(src) : "memory");
}
#define CP_COMMIT() asm volatile("cp.async.commit_group;" ::: "memory")
#define CP_WAIT1() asm volatile("cp.async.wait_group 1;" ::: "memory")
#define CP_WAIT0() asm volatile("cp.async.wait_group 0;" ::: "memory")

__device__ __forceinline__ void ldsm4(uint32_t* r, uint32_t a) {
    asm volatile("ldmatrix.sync.aligned.m8n8.x4.shared.b16 {%0,%1,%2,%3}, [%4];"
                 : "=r"(r[0]), "=r"(r[1]), "=r"(r[2]), "=r"(r[3]) : "r"(a));
}

__device__ __forceinline__ void mma_f16(float* d, const uint32_t* a, uint32_t b0,
                                        uint32_t b1) {
    asm volatile(
        "mma.sync.aligned.m16n8k16.row.col.f32.f16.f16.f32 "
        "{%0,%1,%2,%3}, {%4,%5,%6,%7}, {%8,%9}, {%0,%1,%2,%3};"
        : "+f"(d[0]), "+f"(d[1]), "+f"(d[2]), "+f"(d[3])
        : "r"(a[0]), "r"(a[1]), "r"(a[2]), "r"(a[3]), "r"(b0), "r"(b1));
}

// tile row stride: 64 f16 + 8 pad = 144 bytes (9 x 16B -> conflict-free LDSM)
#define TSTRIDE 144

// ---------------------------------------------------------------------------
// wvec + cvt_w: w_src[k] = sum_o a_src[o]*W[o][k] (warp per k, 256 warps),
// plus f32->f16 conversion of W in the same kernel.
// ---------------------------------------------------------------------------
__global__ __launch_bounds__(256) void wvec_cvtw_kernel(const float* __restrict__ W,
                                                        const float* __restrict__ a_src,
                                                        const float* __restrict__ a_dst) {
    int t = threadIdx.x, lane = t & 31, warp = t >> 5;
    int k = blockIdx.x * 8 + warp;     // 0..255
    float s1 = 0.f, s2 = 0.f;
    #pragma unroll
    for (int q = 0; q < 8; q++) {
        int o = lane + 32 * q;
        float w = W[(size_t)o * FF + k];
        s1 += a_src[o] * w;
        s2 += a_dst[o] * w;
    }
    #pragma unroll
    for (int o = 16; o; o >>= 1) {
        s1 += __shfl_xor_sync(0xFFFFFFFFu, s1, o);
        s2 += __shfl_xor_sync(0xFFFFFFFFu, s2, o);
    }
    if (lane == 0) {
        g_wsrc[k] = s1;
        g_wdst[k] = s2;
    }
    const float4* src = reinterpret_cast<const float4*>(W);
    __half2* dst = reinterpret_cast<__half2*>(g_Wh);
    int gt = blockIdx.x * 256 + t;
    #pragma unroll
    for (int q = 0; q < 2; q++) {
        int i = gt + 8192 * q;
        float4 v = src[i];
        dst[i * 2] = __floats2half2_rn(v.x, v.y);
        dst[i * 2 + 1] = __floats2half2_rn(v.z, v.w);
    }
}

// ---------------------------------------------------------------------------
// score + cvt_x: s_src = x.w_src, s_dst = x.w_dst (warp per row), and emit
// the f16 copy of x while the row is in registers.
// ---------------------------------------------------------------------------
__global__ __launch_bounds__(256) void score_kernel(const float* __restrict__ x) {
    __shared__ float ws[FF], wd[FF];
    int t = threadIdx.x;
    ws[t] = g_wsrc[t];
    wd[t] = g_wdst[t];
    __syncthreads();
    int warp = t >> 5, lane = t & 31;
    int g = blockIdx.x * 8 + warp;
    const float4* xr = reinterpret_cast<const float4*>(x + (size_t)g * FF);
    __half2* xo = reinterpret_cast<__half2*>(g_xh + (size_t)g * FF);
    float s1 = 0.f, s2 = 0.f;
    #pragma unroll
    for (int q = 0; q < 2; q++) {
        int idx = lane + 32 * q;
        float4 v = xr[idx];
        xo[idx * 2] = __floats2half2_rn(v.x, v.y);
        xo[idx * 2 + 1] = __floats2half2_rn(v.z, v.w);
        float4 w1 = *reinterpret_cast<const float4*>(&ws[idx * 4]);
        float4 w2 = *reinterpret_cast<const float4*>(&wd[idx * 4]);
        s1 += v.x * w1.x + v.y * w1.y + v.z * w1.z + v.w * w1.w;
        s2 += v.x * w2.x + v.y * w2.y + v.z * w2.z + v.w * w2.w;
    }
    #pragma unroll
    for (int o = 16; o; o >>= 1) {
        s1 += __shfl_xor_sync(0xFFFFFFFFu, s1, o);
        s2 += __shfl_xor_sync(0xFFFFFFFFu, s2, o);
    }
    if (lane == 0) {
        g_es1[g] = __expf(s1);
        g_es2[g] = __expf(0.2f * s1);
        g_ed1[g] = __expf(s2);
        g_ed2[g] = __expf(0.2f * s2);
    }
}

// ---------------------------------------------------------------------------
// gemm_h v2: h_T[b][f][n] = sum_k W[f][k] * x[b][n][k]  (f16 mma, f32 accum)
// CTA tile m64(f) x n128, 8 warps (2m x 4n), warp m32 x n32 -> acc 32 regs.
// smem 55.3 KB, 3 CTAs/SM; grid 512 -> one balanced wave, 24 warps/SM.
// ---------------------------------------------------------------------------
#define GH_SMEM ((2 * 64 + 2 * 128) * TSTRIDE)   // 55296 B
__global__ __launch_bounds__(256, 3) void gemm_h_kernel() {
    extern __shared__ char smraw[];
    uint32_t su = smem_u32(smraw);
    const uint32_t AB[2] = {su, su + 64 * TSTRIDE};
    const uint32_t XB[2] = {su + 2 * 64 * TSTRIDE,
                            su + 2 * 64 * TSTRIDE + 128 * TSTRIDE};

    int t = threadIdx.x, l = t & 31, w = t >> 5;
    int b = blockIdx.z, n0 = blockIdx.x * 128, m0 = blockIdx.y * 64;
    int mbase = (w & 1) * 32, nbase = (w >> 1) * 32;
    int a_row = (l & 7) + ((l & 8) ? 8 : 0);
    int a_k = (l & 16) ? 16 : 0;
    int b_row = (l & 7) + ((l & 16) ? 8 : 0);
    int b_k = (l & 8) ? 16 : 0;

    const __half* Wsrc = g_Wh + (size_t)m0 * FF;
    const __half* Xsrc = g_xh + ((size_t)b * NN + n0) * FF;

    float acc[2][4][4] = {};

    // A: 64 rows x 8 segs = 512 cp16 (2/thread); X: 128 rows x 8 segs = 1024 (4/thread)
    #define GH_FILL(kc, s)                                                   \
        do {                                                                 \
            _Pragma("unroll")                                                \
            for (int q = 0; q < 2; q++) {                                    \
                int e = t + 256 * q;                                         \
                int fr = e >> 3, sg = e & 7;                                 \
                cp16(AB[s] + fr * TSTRIDE + sg * 16,                         \
                     Wsrc + (size_t)fr * FF + (kc) + sg * 8);                \
            }                                                                \
            _Pragma("unroll")                                                \
            for (int q = 0; q < 4; q++) {                                    \
                int e = t + 256 * q;                                         \
                int fr = e >> 3, sg = e & 7;                                 \
                cp16(XB[s] + fr * TSTRIDE + sg * 16,                         \
                     Xsrc + (size_t)fr * FF + (kc) + sg * 8);                \
            }                                                                \
            CP_COMMIT();                                                     \
        } while (0)

    GH_FILL(0, 0);
    for (int c = 0; c < 4; c++) {
        int s = c & 1;
        if (c < 3) GH_FILL((c + 1) * 64, s ^ 1);
        if (c < 3) CP_WAIT1(); else CP_WAIT0();
        __syncthreads();
        #pragma unroll
        for (int kk = 0; kk < 4; kk++) {
            uint32_t bf[2][4];
            #pragma unroll
            for (int g = 0; g < 2; g++)
                ldsm4(bf[g], XB[s] + (nbase + g * 16 + b_row) * TSTRIDE +
                                 kk * 32 + b_k);
            #pragma unroll
            for (int mt = 0; mt < 2; mt++) {
                uint32_t a[4];
                ldsm4(a, AB[s] + (mbase + mt * 16 + a_row) * TSTRIDE +
                             kk * 32 + a_k);
                #pragma unroll
                for (int g = 0; g < 2; g++) {
                    mma_f16(acc[mt][2 * g], a, bf[g][0], bf[g][1]);
                    mma_f16(acc[mt][2 * g + 1], a, bf[g][2], bf[g][3]);
                }
            }
        }
        __syncthreads();
    }

    #pragma unroll
    for (int mt = 0; mt < 2; mt++) {
        int f = m0 + mbase + mt * 16 + (l >> 2);
        #pragma unroll
        for (int nt = 0; nt < 4; nt++) {
            int n = n0 + nbase + nt * 8 + 2 * (l & 3);
            *reinterpret_cast<__half2*>(&g_hTh[((size_t)b * FF + f) * NN + n]) =
                __floats2half2_rn(acc[mt][nt][0], acc[mt][nt][1]);
            *reinterpret_cast<__half2*>(&g_hTh[((size_t)b * FF + f + 8) * NN + n]) =
                __floats2half2_rn(acc[mt][nt][2], acc[mt][nt][3]);
        }
    }
}

// ---------------------------------------------------------------------------
// attn: fused masked softmax + alpha @ h, f16 mma. EXACT R10 configuration
// (best measured): ITILE=64, 512 threads = 16 warps (2i x 8n), warp m32xn32,
// 2 CTAs/SM, two-sync pipeline.
// p = adj * max(e^s_src * e^s_dst, e^{.2 s_src} * e^{.2 s_dst})  (exact lrelu)
// ---------------------------------------------------------------------------
#define ITILE 64
#define OFF_P0 0
#define OFF_P1 (64 * TSTRIDE)                       // 9216
#define OFF_H0 (2 * 64 * TSTRIDE)                   // 18432
#define OFF_H1 (OFF_H0 + 256 * TSTRIDE)             // 55296
#define OFF_SE (OFF_H1 + 256 * TSTRIDE)             // 92160
#define OFF_SG (OFF_SE + NN * 4)                    // 100352
#define OFF_ES1 (OFF_SG + NN * 4)                   // 108544
#define OFF_ES2 (OFF_ES1 + 256)
#define OFF_INVD (OFF_ES2 + 256)
#define AT_SMEM (OFF_INVD + 256)                    // 109312

__global__ __launch_bounds__(512, 2) void attn_kernel(const int* __restrict__ adj,
                                                      float* __restrict__ out) {
    extern __shared__ char smraw[];
    uint32_t su = smem_u32(smraw);
    float* sE = reinterpret_cast<float*>(smraw + OFF_SE);
    float* sG = reinterpret_cast<float*>(smraw + OFF_SG);
    float* eS1 = reinterpret_cast<float*>(smraw + OFF_ES1);
    float* eS2 = reinterpret_cast<float*>(smraw + OFF_ES2);
    float* invd = reinterpret_cast<float*>(smraw + OFF_INVD);

    int t = threadIdx.x, l = t & 31, w = t >> 5;
    int b = blockIdx.y;
    int i0 = blockIdx.x * ITILE;

    for (int c = t; c < NN; c += 512) {
        sE[c] = g_ed1[b * NN + c];
        sG[c] = g_ed2[b * NN + c];
    }
    if (t < ITILE) {
        eS1[t] = g_es1[b * NN + i0 + t];
        eS2[t] = g_es2[b * NN + i0 + t];
    }
    __syncthreads();

    // p mapping: 8 threads/row, 8 j each (2 int4 quads)
    int pi = t >> 3, jq = t & 7;
    float E1 = eS1[pi], E2 = eS2[pi];
    const int4* adj_row = reinterpret_cast<const int4*>(
                              adj + ((size_t)b * NN + i0 + pi) * NN) + jq * 2;
    const float4* sE4 = reinterpret_cast<const float4*>(sE);
    const float4* sG4 = reinterpret_cast<const float4*>(sG);
    float dreg = 0.f;

    // mma mapping: 2i x 8n warp grid, warp m32 x n32
    int mbase = (w & 1) * 32, nbase = (w >> 1) * 32;
    int a_row = (l & 7) + ((l & 8) ? 8 : 0);
    int a_k = (l & 16) ? 16 : 0;
    int b_row = (l & 7) + ((l & 16) ? 8 : 0);
    int b_k = (l & 8) ? 16 : 0;

    const __half* hsrc = g_hTh + (size_t)b * FF * NN;

    const uint32_t PB[2] = {su + OFF_P0, su + OFF_P1};
    const uint32_t HB[2] = {su + OFF_H0, su + OFF_H1};

    #define AT_HFILL(jc, s)                                                  \
        do {                                                                 \
            _Pragma("unroll")                                                \
            for (int l2 = 0; l2 < 4; l2++) {                                 \
                int e = t + 512 * l2;                                        \
                int fr = e >> 3, sg = e & 7;                                 \
                cp16(HB[s] + fr * TSTRIDE + sg * 16,                         \
                     hsrc + (size_t)fr * NN + (jc) + sg * 8);                \
            }                                                                \
            CP_COMMIT();                                                     \
        } while (0)

    int4 aR[2];
    aR[0] = adj_row[0];
    aR[1] = adj_row[1];
    AT_HFILL(0, 0);

    float acc[2][4][4] = {};

    for (int c = 0; c < CHUNKS; c++) {
        int s = c & 1;
        int jc = c * 64;

        // ---- p(c) from prefetched adj regs ----
        {
            uint32_t pk[4];
            int jb = (jc >> 2) + jq * 2;
            #pragma unroll
            for (int q = 0; q < 2; q++) {
                int4 av = aR[q];
                float4 de = sE4[jb + q];
                float4 dg = sG4[jb + q];
                float p0 = fmaxf(E1 * de.x, E2 * dg.x);
                float p1 = fmaxf(E1 * de.y, E2 * dg.y);
                float p2 = fmaxf(E1 * de.z, E2 * dg.z);
                float p3 = fmaxf(E1 * de.w, E2 * dg.w);
                p0 = av.x ? p0 : 0.f;
                p1 = av.y ? p1 : 0.f;
                p2 = av.z ? p2 : 0.f;
                p3 = av.w ? p3 : 0.f;
                __half2 h0 = __floats2half2_rn(p0, p1);
                __half2 h1 = __floats2half2_rn(p2, p3);
                float2 f0 = __half22float2(h0);
                float2 f1 = __half22float2(h1);
                dreg += (f0.x + f0.y) + (f1.x + f1.y);
                pk[q * 2] = *reinterpret_cast<uint32_t*>(&h0);
                pk[q * 2 + 1] = *reinterpret_cast<uint32_t*>(&h1);
            }
            uint32_t pa = PB[s] + pi * TSTRIDE + jq * 16;
            asm volatile("st.shared.v4.b32 [%0], {%1,%2,%3,%4};" ::"r"(pa),
                         "r"(pk[0]), "r"(pk[1]), "r"(pk[2]), "r"(pk[3]) : "memory");
        }
        // ---- prefetch adj(c+1), issue h(c+1) cp.async ----
        if (c + 1 < CHUNKS) {
            aR[0] = adj_row[(c + 1) * 16];
            aR[1] = adj_row[(c + 1) * 16 + 1];
            AT_HFILL(jc + 64, s ^ 1);
            CP_WAIT1();
        } else {
            CP_WAIT0();
        }
        __syncthreads();

        // ---- f16 tensor-core GEMM on buffers s ----
        #pragma unroll
        for (int kk = 0; kk < 4; kk++) {
            uint32_t bf[2][4];
            #pragma unroll
            for (int g = 0; g < 2; g++)
                ldsm4(bf[g], HB[s] + (nbase + g * 16 + b_row) * TSTRIDE +
                                 kk * 32 + b_k);
            #pragma unroll
            for (int mt = 0; mt < 2; mt++) {
                uint32_t a[4];
                ldsm4(a, PB[s] + (mbase + mt * 16 + a_row) * TSTRIDE +
                             kk * 32 + a_k);
                #pragma unroll
                for (int g = 0; g < 2; g++) {
                    mma_f16(acc[mt][2 * g], a, bf[g][0], bf[g][1]);
                    mma_f16(acc[mt][2 * g + 1], a, bf[g][2], bf[g][3]);
                }
            }
        }
        __syncthreads();
    }

    // ---- denominators (8 threads per row -> shfl over 3 levels) ----
    dreg += __shfl_xor_sync(0xFFFFFFFFu, dreg, 1);
    dreg += __shfl_xor_sync(0xFFFFFFFFu, dreg, 2);
    dreg += __shfl_xor_sync(0xFFFFFFFFu, dreg, 4);
    if ((t & 7) == 0) invd[pi] = (dreg > 0.f) ? (1.f / dreg) : 0.f;
    __syncthreads();

    // ---- epilogue ----
    #pragma unroll
    for (int mt = 0; mt < 2; mt++) {
        int lr = mbase + mt * 16 + (l >> 2);
        float s0 = invd[lr], s1v = invd[lr + 8];
        float* o0 = out + ((size_t)b * NN + i0 + lr) * FF + nbase;
        float* o1 = o0 + (size_t)8 * FF;
        #pragma unroll
        for (int nt = 0; nt < 4; nt++) {
            int cofs = nt * 8 + 2 * (l & 3);
            *reinterpret_cast<float2*>(o0 + cofs) =
                make_float2(acc[mt][nt][0] * s0, acc[mt][nt][1] * s0);
            *reinterpret_cast<float2*>(o1 + cofs) =
                make_float2(acc[mt][nt][2] * s1v, acc[mt][nt][3] * s1v);
        }
    }
}

// ---------------------------------------------------------------------------
extern "C" void kernel_launch(void* const* d_in, const int* in_sizes, int n_in,
                              void* d_out, int out_size) {
    const float* x     = (const float*)d_in[0];  // (B,N,F_in)
    const int*   adj   = (const int*)d_in[1];    // (B,N,N)
    const float* W     = (const float*)d_in[2];  // (F_out,F_in)
    const float* a_src = (const float*)d_in[3];  // (F_out)
    const float* a_dst = (const float*)d_in[4];  // (F_out)
    float* out = (float*)d_out;                  // (B,N,F_out)

    (void)in_sizes; (void)n_in; (void)out_size;

    // w = W^T a (warp-per-k) + W f16 conversion, one kernel
    wvec_cvtw_kernel<<<32, 256>>>(W, a_src, a_dst);
    // scores + x f16 conversion, one kernel
    score_kernel<<<(BB * NN) / 8, 256>>>(x);
    // h_T = W @ x^T (f16 tensor cores, m64xn128 tiles, 3 CTAs/SM)
    cudaFuncSetAttribute(gemm_h_kernel, cudaFuncAttributeMaxDynamicSharedMemorySize,
                         GH_SMEM);
    gemm_h_kernel<<<dim3(NN / 128, FF / 64, BB), 256, GH_SMEM>>>();
    // fused masked softmax + alpha @ h (exact R10 config)
    cudaFuncSetAttribute(attn_kernel, cudaFuncAttributeMaxDynamicSharedMemorySize,
                         AT_SMEM);
    attn_kernel<<<dim3(NN / ITILE, BB), 512, AT_SMEM>>>(adj, out);
}